// round 8
// baseline (speedup 1.0000x reference)
#include <cuda_runtime.h>
#include <cuda_fp16.h>
#include <cstdint>
#include <cstddef>

#define VIN  4096      // 16^3
#define VOUT 262144    // 64^3
#define WPAD 72        // padded row stride (elems) to kill bank conflicts

// ---------------- device scratch (no allocation allowed) ----------------
__device__ float g_X1[128];   // [n*64+c] sum x
__device__ float g_X2[128];   // [n*64+c] sum x^2
__device__ __align__(16) unsigned short g_WgH[64 * WPAD];  // fp16 Wg[o][c], padded rows
__device__ float g_B[128];    // [n][o] fused bias
__device__ float g_rstd[2];

// ---------------- helpers ----------------
__device__ __forceinline__ uint32_t smem_u32(const void* p) {
    uint32_t a;
    asm("{ .reg .u64 t; cvta.to.shared.u64 t, %1; cvt.u32.u64 %0, t; }" : "=r"(a) : "l"(p));
    return a;
}
__device__ __forceinline__ uint32_t pack_f16x2(float lo, float hi) {
    __half2 h = __floats2half2_rn(lo, hi);   // .x = lo, .y = hi
    return *(uint32_t*)&h;
}
__device__ __forceinline__ void mma_f16(float* c, const uint32_t* a, uint32_t b0, uint32_t b1) {
    asm volatile(
        "mma.sync.aligned.m16n8k16.row.col.f32.f16.f16.f32 "
        "{%0,%1,%2,%3}, {%4,%5,%6,%7}, {%8,%9}, {%0,%1,%2,%3};"
        : "+f"(c[0]), "+f"(c[1]), "+f"(c[2]), "+f"(c[3])
        : "r"(a[0]), "r"(a[1]), "r"(a[2]), "r"(a[3]), "r"(b0), "r"(b1));
}
__device__ __forceinline__ void ldmat_x4(uint32_t* r, uint32_t addr) {
    asm volatile("ldmatrix.sync.aligned.m8n8.x4.shared.b16 {%0,%1,%2,%3}, [%4];"
                 : "=r"(r[0]), "=r"(r[1]), "=r"(r[2]), "=r"(r[3]) : "r"(addr));
}

// ---------------- kernel 1: per-(n,c) sums ----------------
__global__ void __launch_bounds__(512)
k_stats(const float* __restrict__ x) {
    const int nc = blockIdx.x;
    const float4* p = (const float4*)(x + (size_t)nc * VIN);
    float a1 = 0.f, a2 = 0.f;
#pragma unroll
    for (int i = 0; i < 2; ++i) {
        float4 v = p[threadIdx.x + i * 512];
        a1 += v.x + v.y + v.z + v.w;
        a2 += v.x * v.x + v.y * v.y + v.z * v.z + v.w * v.w;
    }
#pragma unroll
    for (int off = 16; off; off >>= 1) {
        a1 += __shfl_xor_sync(0xffffffffu, a1, off);
        a2 += __shfl_xor_sync(0xffffffffu, a2, off);
    }
    __shared__ float s1[16], s2[16];
    int wid = threadIdx.x >> 5, lid = threadIdx.x & 31;
    if (lid == 0) { s1[wid] = a1; s2[wid] = a2; }
    __syncthreads();
    if (threadIdx.x == 0) {
        float t1 = 0.f, t2 = 0.f;
        for (int w = 0; w < 16; ++w) { t1 += s1[w]; t2 += s2[w]; }
        g_X1[nc] = t1;
        g_X2[nc] = t2;
    }
}

// ---------------- kernel 2: closed-form stats + fp16 weights ----------------
__global__ void k_prep(const float* __restrict__ w_ct,
                       const float* __restrict__ b_ct,
                       const float* __restrict__ gamma,
                       const float* __restrict__ beta,
                       const float* __restrict__ w_pw) {
    __shared__ float sS1[64], sS2[64];
    __shared__ float sMean[2], sRstd[2];
    const int tid = threadIdx.x;

    if (tid < 64) {
        float s1 = 0.f, s2 = 0.f;
        for (int t = 0; t < 64; ++t) {
            float w = w_ct[tid * 64 + t];
            s1 += w;
            s2 += w * w;
        }
        sS1[tid] = s1;
        sS2[tid] = s2;
    }
    __syncthreads();

    if (tid < 2) {
        double sy = 0.0, sy2 = 0.0;
        for (int c = 0; c < 64; ++c) {
            double X1 = (double)g_X1[tid * 64 + c];
            double X2 = (double)g_X2[tid * 64 + c];
            double b  = (double)b_ct[c];
            double S1 = (double)sS1[c];
            double S2 = (double)sS2[c];
            sy  += S1 * X1 + (double)VOUT * b;
            sy2 += S2 * X2 + 2.0 * b * S1 * X1 + (double)VOUT * b * b;
        }
        double mean = sy / 16777216.0;
        double var  = sy2 / 16777216.0 - mean * mean;
        double rstd = 1.0 / sqrt(var + 1e-5);
        sMean[tid] = (float)mean;
        sRstd[tid] = (float)rstd;
        g_rstd[tid] = (float)rstd;
    }
    __syncthreads();

    // Wg[o][c] = w_pw[o,c]*gamma[c] -> fp16, padded rows
    for (int idx = tid; idx < 4096; idx += 256) {
        int o = idx >> 6, c = idx & 63;
        float v = w_pw[o * 64 + c] * gamma[c];
        __half hv = __float2half_rn(v);
        g_WgH[o * WPAD + c] = *(unsigned short*)&hv;
    }
    // zero padding columns
    for (int idx = tid; idx < 64 * 8; idx += 256) {
        int o = idx >> 3, c = 64 + (idx & 7);
        g_WgH[o * WPAD + c] = 0;
    }

    if (tid < 128) {
        int n = tid >> 6, o = tid & 63;
        float mean = sMean[n], rstd = sRstd[n];
        float acc1 = 0.f, acc2 = 0.f;
        for (int c = 0; c < 64; ++c) {
            float wpc = w_pw[o * 64 + c];
            acc1 += wpc * gamma[c] * (b_ct[c] - mean);
            acc2 += wpc * beta[c];
        }
        g_B[tid] = rstd * acc1 + acc2;
    }
}

// ---------------- kernel 3: HMMA fp16 scatter-GEMM (1 term-group) ----------------
// Block = (n, dout, h): D[o=64][s=256] = Wg[64x64] x z[64x256],
// z[c][s] = w_ct[c, i, s>>6, (s&3)] * x[n, c, d, h, (s&63)>>2]
// out[n, o, dout, 4h + s>>6, s&63] = rstd * D + B[n][o]
__global__ void __launch_bounds__(256, 2)
k_main(const float* __restrict__ x,
       const float* __restrict__ w_ct,
       float* __restrict__ out) {
    __shared__ __align__(16) unsigned short sWg[64 * WPAD];
    __shared__ __align__(16) float sXT[16 * WPAD];   // [w][c] padded
    __shared__ __align__(16) float sWT[16 * WPAD];   // [jk][c] padded (i fixed)
    __shared__ float sB[64];

    const int tid = threadIdx.x;
    const int warp = tid >> 5;
    const int l = tid & 31;

    const int b = blockIdx.x;
    const int n = b >> 10;
    const int dout = (b >> 4) & 63;
    const int h = b & 15;
    const int d = dout >> 2, i = dout & 3;

    // ---- stage operands ----
    {
        const uint4* gh = (const uint4*)g_WgH;
        uint4* sh = (uint4*)sWg;
        for (int idx = tid; idx < 576; idx += 256)   // 64*72*2B / 16B
            sh[idx] = gh[idx];
        const int c = tid >> 2, q = tid & 3;
        float4 xv = *(const float4*)(x + (size_t)(n * 64 + c) * VIN + d * 256 + h * 16 + q * 4);
        sXT[(q * 4 + 0) * WPAD + c] = xv.x;
        sXT[(q * 4 + 1) * WPAD + c] = xv.y;
        sXT[(q * 4 + 2) * WPAD + c] = xv.z;
        sXT[(q * 4 + 3) * WPAD + c] = xv.w;
        float4 wv = *(const float4*)(w_ct + c * 64 + i * 16 + q * 4);
        sWT[(q * 4 + 0) * WPAD + c] = wv.x;
        sWT[(q * 4 + 1) * WPAD + c] = wv.y;
        sWT[(q * 4 + 2) * WPAD + c] = wv.z;
        sWT[(q * 4 + 3) * WPAD + c] = wv.w;
        if (tid < 64) sB[tid] = g_B[n * 64 + tid];
    }
    __syncthreads();

    const float rstd = g_rstd[n];

    // per-warp column slab: s = warp*32 + nt*8 + (l>>2)
    const int sBase = warp * 32;
    const int lq = l >> 2;
    int xrow[4], wrow[4];
#pragma unroll
    for (int nt = 0; nt < 4; ++nt) {
        int s = sBase + nt * 8 + lq;
        int wout = s & 63;
        xrow[nt] = (wout >> 2) * (WPAD / 2);                   // float2 row base
        wrow[nt] = ((s >> 6) * 4 + (wout & 3)) * (WPAD / 2);
    }
    const float2* xt2 = (const float2*)sXT;
    const float2* wt2 = (const float2*)sWT;

    float acc[4][4][4];
#pragma unroll
    for (int mt = 0; mt < 4; ++mt)
#pragma unroll
        for (int nt = 0; nt < 4; ++nt)
#pragma unroll
            for (int r = 0; r < 4; ++r) acc[mt][nt][r] = 0.f;

    // A-fragment ldmatrix addressing: row = l&15, col-half = (l>>4)*8
    const uint32_t aBase = smem_u32(sWg);
    const int o_lm = l & 15;
    const int c_lm = (l & 16) >> 1;

#pragma unroll
    for (int kc = 0; kc < 4; ++kc) {
        uint32_t aF[4][4];
#pragma unroll
        for (int mt = 0; mt < 4; ++mt) {
            uint32_t off = (uint32_t)(((mt * 16 + o_lm) * WPAD + kc * 16 + c_lm) * 2);
            ldmat_x4(aF[mt], aBase + off);
        }
        const int cp = kc * 8 + (l & 3);
#pragma unroll
        for (int nt = 0; nt < 4; ++nt) {
            float2 x0 = xt2[xrow[nt] + cp];
            float2 w0 = wt2[wrow[nt] + cp];
            float2 x1 = xt2[xrow[nt] + cp + 4];
            float2 w1 = wt2[wrow[nt] + cp + 4];
            uint32_t b0 = pack_f16x2(x0.x * w0.x, x0.y * w0.y);
            uint32_t b1 = pack_f16x2(x1.x * w1.x, x1.y * w1.y);
#pragma unroll
            for (int mt = 0; mt < 4; ++mt)
                mma_f16(acc[mt][nt], aF[mt], b0, b1);
        }
    }

    // ---- epilogue: rstd scale + fused bias, coalesced float2 stores ----
    const size_t outBase = (size_t)n * 64 * VOUT + (size_t)dout * 4096 + (size_t)h * 256;
#pragma unroll
    for (int mt = 0; mt < 4; ++mt) {
        const int o0 = mt * 16 + (l >> 2);
        const int o1 = o0 + 8;
        const float B0 = sB[o0], B1 = sB[o1];
        float* p0 = out + outBase + (size_t)o0 * VOUT;
        float* p1 = out + outBase + (size_t)o1 * VOUT;
#pragma unroll
        for (int nt = 0; nt < 4; ++nt) {
            const int s = sBase + nt * 8 + 2 * (l & 3);
            float2 v0, v1;
            v0.x = fmaf(rstd, acc[mt][nt][0], B0);
            v0.y = fmaf(rstd, acc[mt][nt][1], B0);
            v1.x = fmaf(rstd, acc[mt][nt][2], B1);
            v1.y = fmaf(rstd, acc[mt][nt][3], B1);
            *(float2*)(p0 + s) = v0;
            *(float2*)(p1 + s) = v1;
        }
    }
}

extern "C" void kernel_launch(void* const* d_in, const int* in_sizes, int n_in,
                              void* d_out, int out_size) {
    (void)in_sizes; (void)n_in; (void)out_size;
    const float* x     = (const float*)d_in[0];
    const float* w_ct  = (const float*)d_in[1];
    const float* b_ct  = (const float*)d_in[2];
    const float* gamma = (const float*)d_in[3];
    const float* beta  = (const float*)d_in[4];
    const float* w_pw  = (const float*)d_in[5];
    float* out = (float*)d_out;

    k_stats<<<128, 512>>>(x);
    k_prep<<<1, 256>>>(w_ct, b_ct, gamma, beta, w_pw);
    k_main<<<2048, 256>>>(x, w_ct, out);
}

// round 9
// speedup vs baseline: 1.3132x; 1.3132x over previous
#include <cuda_runtime.h>
#include <cstdint>
#include <cstddef>

#define VIN  4096      // 16^3
#define VOUT 262144    // 64^3
#define PADF 68        // padded fp32 row stride (68 mod 32 = 4 -> conflict-free frags)

// ---------------- device scratch (no allocation allowed) ----------------
__device__ float g_X1[128];   // [n*64+c] sum x
__device__ float g_X2[128];   // [n*64+c] sum x^2
__device__ __align__(16) float g_WgF[64 * PADF];  // tf32-rounded Wg[o][c], padded rows
__device__ float g_B[128];    // [n][o] fused bias
__device__ float g_rstd[2];

// ---------------- helpers ----------------
__device__ __forceinline__ uint32_t tf32_rna(float v) {
    uint32_t r;
    asm("cvt.rna.tf32.f32 %0, %1;" : "=r"(r) : "f"(v));
    return r;
}
__device__ __forceinline__ void mma_tf32(float* c, const uint32_t* a, uint32_t b0, uint32_t b1) {
    asm volatile(
        "mma.sync.aligned.m16n8k8.row.col.f32.tf32.tf32.f32 "
        "{%0,%1,%2,%3}, {%4,%5,%6,%7}, {%8,%9}, {%0,%1,%2,%3};"
        : "+f"(c[0]), "+f"(c[1]), "+f"(c[2]), "+f"(c[3])
        : "r"(a[0]), "r"(a[1]), "r"(a[2]), "r"(a[3]), "r"(b0), "r"(b1));
}

// ---------------- kernel 1: per-(n,c) sums ----------------
__global__ void __launch_bounds__(256)
k_stats(const float* __restrict__ x) {
    const int nc = blockIdx.x;
    const float4* p = (const float4*)(x + (size_t)nc * VIN);
    float a1 = 0.f, a2 = 0.f;
#pragma unroll
    for (int i = 0; i < 4; ++i) {
        float4 v = p[threadIdx.x + i * 256];
        a1 += v.x + v.y + v.z + v.w;
        a2 += v.x * v.x + v.y * v.y + v.z * v.z + v.w * v.w;
    }
#pragma unroll
    for (int off = 16; off; off >>= 1) {
        a1 += __shfl_xor_sync(0xffffffffu, a1, off);
        a2 += __shfl_xor_sync(0xffffffffu, a2, off);
    }
    __shared__ float s1[8], s2[8];
    int wid = threadIdx.x >> 5, lid = threadIdx.x & 31;
    if (lid == 0) { s1[wid] = a1; s2[wid] = a2; }
    __syncthreads();
    if (threadIdx.x == 0) {
        float t1 = 0.f, t2 = 0.f;
        for (int w = 0; w < 8; ++w) { t1 += s1[w]; t2 += s2[w]; }
        g_X1[nc] = t1;
        g_X2[nc] = t2;
    }
}

// ---------------- kernel 2: closed-form stats + tf32 weights ----------------
__global__ void k_prep(const float* __restrict__ w_ct,
                       const float* __restrict__ b_ct,
                       const float* __restrict__ gamma,
                       const float* __restrict__ beta,
                       const float* __restrict__ w_pw) {
    __shared__ float sS1[64], sS2[64];
    __shared__ float sMean[2], sRstd[2];
    const int tid = threadIdx.x;

    if (tid < 64) {
        float s1 = 0.f, s2 = 0.f;
        for (int t = 0; t < 64; ++t) {
            float w = w_ct[tid * 64 + t];
            s1 += w;
            s2 += w * w;
        }
        sS1[tid] = s1;
        sS2[tid] = s2;
    }
    __syncthreads();

    if (tid < 2) {
        double sy = 0.0, sy2 = 0.0;
        for (int c = 0; c < 64; ++c) {
            double X1 = (double)g_X1[tid * 64 + c];
            double X2 = (double)g_X2[tid * 64 + c];
            double b  = (double)b_ct[c];
            double S1 = (double)sS1[c];
            double S2 = (double)sS2[c];
            sy  += S1 * X1 + (double)VOUT * b;
            sy2 += S2 * X2 + 2.0 * b * S1 * X1 + (double)VOUT * b * b;
        }
        double mean = sy / 16777216.0;
        double var  = sy2 / 16777216.0 - mean * mean;
        double rstd = 1.0 / sqrt(var + 1e-5);
        sMean[tid] = (float)mean;
        sRstd[tid] = (float)rstd;
        g_rstd[tid] = (float)rstd;
    }
    __syncthreads();

    // Wg[o][c] = w_pw[o,c]*gamma[c] -> tf32-rounded fp32, padded rows (pad = 0)
    for (int idx = tid; idx < 64 * PADF; idx += 256) {
        int o = idx / PADF, c = idx % PADF;
        float v = 0.f;
        if (c < 64) {
            float w = w_pw[o * 64 + c] * gamma[c];
            v = __uint_as_float(tf32_rna(w));
        }
        g_WgF[idx] = v;
    }

    if (tid < 128) {
        int n = tid >> 6, o = tid & 63;
        float mean = sMean[n], rstd = sRstd[n];
        float acc1 = 0.f, acc2 = 0.f;
        for (int c = 0; c < 64; ++c) {
            float wpc = w_pw[o * 64 + c];
            acc1 += wpc * gamma[c] * (b_ct[c] - mean);
            acc2 += wpc * beta[c];
        }
        g_B[tid] = rstd * acc1 + acc2;
    }
}

// ---------------- kernel 3: tf32 HMMA scatter-GEMM (1 group) ----------------
// Block = (n, dout, h): D[o=64][s=256] = Wg[64x64] x z[64x256],
// z[c][s] = w_ct[c, i, s>>6, s&3] * x[n, c, d, h, (s&63)>>2]
// out[n, o, dout, 4h + (s>>6), s&63] = rstd * D + B[n][o]
__global__ void __launch_bounds__(256, 2)
k_main(const float* __restrict__ x,
       const float* __restrict__ w_ct,
       float* __restrict__ out) {
    __shared__ __align__(16) float sWg[64 * PADF];  // [o][c] tf32 bits
    __shared__ __align__(16) float sXT[16 * PADF];  // [w][c]
    __shared__ __align__(16) float sWT[16 * PADF];  // [jk][c] (i fixed)
    __shared__ float sB[64];

    const int tid = threadIdx.x;
    const int warp = tid >> 5;
    const int l = tid & 31;
    const int lq = l >> 2, lr = l & 3;

    const int b = blockIdx.x;
    const int n = b >> 10;
    const int dout = (b >> 4) & 63;
    const int h = b & 15;
    const int d = dout >> 2, i = dout & 3;

    // ---- stage operands ----
    {
        const float4* gw = (const float4*)g_WgF;
        float4* sw = (float4*)sWg;
        for (int idx = tid; idx < 64 * PADF / 4; idx += 256)   // 1088 float4
            sw[idx] = gw[idx];
        const int c = tid >> 2, q = tid & 3;
        float4 xv = *(const float4*)(x + (size_t)(n * 64 + c) * VIN + d * 256 + h * 16 + q * 4);
        sXT[(q * 4 + 0) * PADF + c] = xv.x;
        sXT[(q * 4 + 1) * PADF + c] = xv.y;
        sXT[(q * 4 + 2) * PADF + c] = xv.z;
        sXT[(q * 4 + 3) * PADF + c] = xv.w;
        float4 wv = *(const float4*)(w_ct + c * 64 + i * 16 + q * 4);
        sWT[(q * 4 + 0) * PADF + c] = wv.x;
        sWT[(q * 4 + 1) * PADF + c] = wv.y;
        sWT[(q * 4 + 2) * PADF + c] = wv.z;
        sWT[(q * 4 + 3) * PADF + c] = wv.w;
        if (tid < 64) sB[tid] = g_B[n * 64 + tid];
    }
    __syncthreads();

    const float rstd = g_rstd[n];

    // per-warp column slab: s = sBase + nt*8 + lq
    const int sBase = warp * 32;
    int xoff[4], woff[4];
#pragma unroll
    for (int nt = 0; nt < 4; ++nt) {
        int s = sBase + nt * 8 + lq;
        xoff[nt] = (((s & 63) >> 2)) * PADF;
        woff[nt] = ((s >> 6) * 4 + (s & 3)) * PADF;
    }

    float acc[4][4][4];
#pragma unroll
    for (int mt = 0; mt < 4; ++mt)
#pragma unroll
        for (int nt = 0; nt < 4; ++nt)
#pragma unroll
            for (int r = 0; r < 4; ++r) acc[mt][nt][r] = 0.f;

#pragma unroll
    for (int ks = 0; ks < 8; ++ks) {
        const int cb = ks * 8 + lr;
        // A fragments: a0 = Wg[mt*16+lq][cb], a1 = +8 rows, a2 = +4 cols, a3 = both
        uint32_t aF[4][4];
#pragma unroll
        for (int mt = 0; mt < 4; ++mt) {
            const int base = (mt * 16 + lq) * PADF + cb;
            aF[mt][0] = __float_as_uint(sWg[base]);
            aF[mt][1] = __float_as_uint(sWg[base + 8 * PADF]);
            aF[mt][2] = __float_as_uint(sWg[base + 4]);
            aF[mt][3] = __float_as_uint(sWg[base + 8 * PADF + 4]);
        }
#pragma unroll
        for (int nt = 0; nt < 4; ++nt) {
            float z0 = sXT[xoff[nt] + cb] * sWT[woff[nt] + cb];
            float z1 = sXT[xoff[nt] + cb + 4] * sWT[woff[nt] + cb + 4];
            uint32_t b0 = tf32_rna(z0);
            uint32_t b1 = tf32_rna(z1);
#pragma unroll
            for (int mt = 0; mt < 4; ++mt)
                mma_tf32(acc[mt][nt], aF[mt], b0, b1);
        }
    }

    // ---- epilogue: rstd scale + fused bias, coalesced float2 stores ----
    const size_t outBase = (size_t)n * 64 * VOUT + (size_t)dout * 4096 + (size_t)h * 256;
#pragma unroll
    for (int mt = 0; mt < 4; ++mt) {
        const int o0 = mt * 16 + lq;
        const int o1 = o0 + 8;
        const float B0 = sB[o0], B1 = sB[o1];
        float* p0 = out + outBase + (size_t)o0 * VOUT;
        float* p1 = out + outBase + (size_t)o1 * VOUT;
#pragma unroll
        for (int nt = 0; nt < 4; ++nt) {
            const int s = sBase + nt * 8 + 2 * lr;
            float2 v0, v1;
            v0.x = fmaf(rstd, acc[mt][nt][0], B0);
            v0.y = fmaf(rstd, acc[mt][nt][1], B0);
            v1.x = fmaf(rstd, acc[mt][nt][2], B1);
            v1.y = fmaf(rstd, acc[mt][nt][3], B1);
            *(float2*)(p0 + s) = v0;
            *(float2*)(p1 + s) = v1;
        }
    }
}

extern "C" void kernel_launch(void* const* d_in, const int* in_sizes, int n_in,
                              void* d_out, int out_size) {
    (void)in_sizes; (void)n_in; (void)out_size;
    const float* x     = (const float*)d_in[0];
    const float* w_ct  = (const float*)d_in[1];
    const float* b_ct  = (const float*)d_in[2];
    const float* gamma = (const float*)d_in[3];
    const float* beta  = (const float*)d_in[4];
    const float* w_pw  = (const float*)d_in[5];
    float* out = (float*)d_out;

    k_stats<<<128, 256>>>(x);
    k_prep<<<1, 256>>>(w_ct, b_ct, gamma, beta, w_pw);
    k_main<<<2048, 256>>>(x, w_ct, out);
}

// round 11
// speedup vs baseline: 1.3610x; 1.0364x over previous
#include <cuda_runtime.h>
#include <cstdint>
#include <cstddef>

#define VIN  4096      // 16^3
#define VOUT 262144    // 64^3
#define PADF 68        // padded fp32 row stride (68 mod 32 = 4 -> conflict-free frags)

// ---------------- device scratch (no allocation allowed) ----------------
__device__ float g_X1[128];   // [n*64+c] sum x
__device__ float g_X2[128];   // [n*64+c] sum x^2
__device__ __align__(16) float g_WgF[64 * PADF];  // tf32-rounded Wg[o][c], padded rows
__device__ float g_B[128];    // [n][o] fused bias
__device__ float g_rstd[2];

// ---------------- helpers ----------------
__device__ __forceinline__ uint32_t tf32_rna(float v) {
    uint32_t r;
    asm("cvt.rna.tf32.f32 %0, %1;" : "=r"(r) : "f"(v));
    return r;
}
__device__ __forceinline__ void mma_tf32(float* c, const uint32_t* a, uint32_t b0, uint32_t b1) {
    asm volatile(
        "mma.sync.aligned.m16n8k8.row.col.f32.tf32.tf32.f32 "
        "{%0,%1,%2,%3}, {%4,%5,%6,%7}, {%8,%9}, {%0,%1,%2,%3};"
        : "+f"(c[0]), "+f"(c[1]), "+f"(c[2]), "+f"(c[3])
        : "r"(a[0]), "r"(a[1]), "r"(a[2]), "r"(a[3]), "r"(b0), "r"(b1));
}
__device__ __forceinline__ void stcs2(float* p, float2 v) {
    asm volatile("st.global.cs.v2.f32 [%0], {%1, %2};" :: "l"(p), "f"(v.x), "f"(v.y) : "memory");
}

// ---------------- kernel 1: per-(n,c) sums ----------------
__global__ void __launch_bounds__(256)
k_stats(const float* __restrict__ x) {
    const int nc = blockIdx.x;
    const float4* p = (const float4*)(x + (size_t)nc * VIN);
    float a1 = 0.f, a2 = 0.f;
#pragma unroll
    for (int i = 0; i < 4; ++i) {
        float4 v = p[threadIdx.x + i * 256];
        a1 += v.x + v.y + v.z + v.w;
        a2 += v.x * v.x + v.y * v.y + v.z * v.z + v.w * v.w;
    }
#pragma unroll
    for (int off = 16; off; off >>= 1) {
        a1 += __shfl_xor_sync(0xffffffffu, a1, off);
        a2 += __shfl_xor_sync(0xffffffffu, a2, off);
    }
    __shared__ float s1[8], s2[8];
    int wid = threadIdx.x >> 5, lid = threadIdx.x & 31;
    if (lid == 0) { s1[wid] = a1; s2[wid] = a2; }
    __syncthreads();
    if (threadIdx.x == 0) {
        float t1 = 0.f, t2 = 0.f;
        for (int w = 0; w < 8; ++w) { t1 += s1[w]; t2 += s2[w]; }
        g_X1[nc] = t1;
        g_X2[nc] = t2;
    }
}

// ---------------- kernel 2: closed-form stats + tf32 weights ----------------
__global__ void k_prep(const float* __restrict__ w_ct,
                       const float* __restrict__ b_ct,
                       const float* __restrict__ gamma,
                       const float* __restrict__ beta,
                       const float* __restrict__ w_pw) {
    __shared__ float sS1[64], sS2[64];
    __shared__ float sMean[2], sRstd[2];
    const int tid = threadIdx.x;

    if (tid < 64) {
        float s1 = 0.f, s2 = 0.f;
        for (int t = 0; t < 64; ++t) {
            float w = w_ct[tid * 64 + t];
            s1 += w;
            s2 += w * w;
        }
        sS1[tid] = s1;
        sS2[tid] = s2;
    }
    __syncthreads();

    if (tid < 2) {
        double sy = 0.0, sy2 = 0.0;
        for (int c = 0; c < 64; ++c) {
            double X1 = (double)g_X1[tid * 64 + c];
            double X2 = (double)g_X2[tid * 64 + c];
            double b  = (double)b_ct[c];
            double S1 = (double)sS1[c];
            double S2 = (double)sS2[c];
            sy  += S1 * X1 + (double)VOUT * b;
            sy2 += S2 * X2 + 2.0 * b * S1 * X1 + (double)VOUT * b * b;
        }
        double mean = sy / 16777216.0;
        double var  = sy2 / 16777216.0 - mean * mean;
        double rstd = 1.0 / sqrt(var + 1e-5);
        sMean[tid] = (float)mean;
        sRstd[tid] = (float)rstd;
        g_rstd[tid] = (float)rstd;
    }
    __syncthreads();

    // Wg[o][c] = w_pw[o,c]*gamma[c] -> tf32-rounded fp32, padded rows (pad = 0)
    for (int idx = tid; idx < 64 * PADF; idx += 256) {
        int o = idx / PADF, c = idx % PADF;
        float v = 0.f;
        if (c < 64) {
            float w = w_pw[o * 64 + c] * gamma[c];
            v = __uint_as_float(tf32_rna(w));
        }
        g_WgF[idx] = v;
    }

    if (tid < 128) {
        int n = tid >> 6, o = tid & 63;
        float mean = sMean[n], rstd = sRstd[n];
        float acc1 = 0.f, acc2 = 0.f;
        for (int c = 0; c < 64; ++c) {
            float wpc = w_pw[o * 64 + c];
            acc1 += wpc * gamma[c] * (b_ct[c] - mean);
            acc2 += wpc * beta[c];
        }
        g_B[tid] = rstd * acc1 + acc2;
    }
}

// ---------------- kernel 3: tf32 HMMA scatter-GEMM (64o x 128s tiles) ----------------
// Block = (n, dout, h, T): D[o=64][s=128T..128T+127], s indexes (j = s>>6, wout = s&63)
// z[c][s] = w_ct[c, i, s>>6, s&3] * x[n, c, d, h, (s&63)>>2]
// out[n, o, dout, 4h + (s>>6), s&63] = rstd * D + B[n][o]
__global__ void __launch_bounds__(128, 4)
k_main(const float* __restrict__ x,
       const float* __restrict__ w_ct,
       float* __restrict__ out) {
    __shared__ __align__(16) float sWg[64 * PADF];  // [o][c] tf32 bits
    __shared__ __align__(16) float sXT[16 * PADF];  // [w][c]
    __shared__ __align__(16) float sWT[16 * PADF];  // [jk][c] (i fixed)
    __shared__ float sB[64];

    const int tid = threadIdx.x;
    const int warp = tid >> 5;
    const int l = tid & 31;
    const int lq = l >> 2, lr = l & 3;

    const int b = blockIdx.x;
    const int n = b >> 11;
    const int dout = (b >> 5) & 63;
    const int h = (b >> 1) & 15;
    const int T = b & 1;
    const int d = dout >> 2, i = dout & 3;

    // ---- stage operands ----
    {
        const float4* gw = (const float4*)g_WgF;
        float4* sw = (float4*)sWg;
        for (int idx = tid; idx < 64 * PADF / 4; idx += 128)   // 1088 float4
            sw[idx] = gw[idx];
        for (int idx = tid; idx < 256; idx += 128) {
            const int c = idx >> 2, q = idx & 3;
            float4 xv = *(const float4*)(x + (size_t)(n * 64 + c) * VIN + d * 256 + h * 16 + q * 4);
            sXT[(q * 4 + 0) * PADF + c] = xv.x;
            sXT[(q * 4 + 1) * PADF + c] = xv.y;
            sXT[(q * 4 + 2) * PADF + c] = xv.z;
            sXT[(q * 4 + 3) * PADF + c] = xv.w;
            float4 wv = *(const float4*)(w_ct + c * 64 + i * 16 + q * 4);
            sWT[(q * 4 + 0) * PADF + c] = wv.x;
            sWT[(q * 4 + 1) * PADF + c] = wv.y;
            sWT[(q * 4 + 2) * PADF + c] = wv.z;
            sWT[(q * 4 + 3) * PADF + c] = wv.w;
        }
        if (tid < 64) sB[tid] = g_B[n * 64 + tid];
    }
    __syncthreads();

    const float rstd = g_rstd[n];

    // per-warp column slab: s = sBase + nt*8 + lq
    const int sBase = T * 128 + warp * 32;
    int xoff[4], woff[4];
#pragma unroll
    for (int nt = 0; nt < 4; ++nt) {
        int s = sBase + nt * 8 + lq;
        xoff[nt] = (((s & 63) >> 2)) * PADF;
        woff[nt] = ((s >> 6) * 4 + (s & 3)) * PADF;
    }

    float acc[4][4][4];
#pragma unroll
    for (int mt = 0; mt < 4; ++mt)
#pragma unroll
        for (int nt = 0; nt < 4; ++nt)
#pragma unroll
            for (int r = 0; r < 4; ++r) acc[mt][nt][r] = 0.f;

#pragma unroll
    for (int ks = 0; ks < 8; ++ks) {
        const int cb = ks * 8 + lr;
        // A fragments: a0 = Wg[mt*16+lq][cb], a1 = +8 rows, a2 = +4 cols, a3 = both
        uint32_t aF[4][4];
#pragma unroll
        for (int mt = 0; mt < 4; ++mt) {
            const int base = (mt * 16 + lq) * PADF + cb;
            aF[mt][0] = __float_as_uint(sWg[base]);
            aF[mt][1] = __float_as_uint(sWg[base + 8 * PADF]);
            aF[mt][2] = __float_as_uint(sWg[base + 4]);
            aF[mt][3] = __float_as_uint(sWg[base + 8 * PADF + 4]);
        }
#pragma unroll
        for (int nt = 0; nt < 4; ++nt) {
            float z0 = sXT[xoff[nt] + cb] * sWT[woff[nt] + cb];
            float z1 = sXT[xoff[nt] + cb + 4] * sWT[woff[nt] + cb + 4];
            uint32_t b0 = tf32_rna(z0);
            uint32_t b1 = tf32_rna(z1);
#pragma unroll
            for (int mt = 0; mt < 4; ++mt)
                mma_tf32(acc[mt][nt], aF[mt], b0, b1);
        }
    }

    // ---- epilogue: rstd scale + fused bias, coalesced streaming float2 stores ----
    const size_t outBase = (size_t)n * 64 * VOUT + (size_t)dout * 4096 + (size_t)h * 256;
#pragma unroll
    for (int mt = 0; mt < 4; ++mt) {
        const int o0 = mt * 16 + lq;
        const int o1 = o0 + 8;
        const float B0 = sB[o0], B1 = sB[o1];
        float* p0 = out + outBase + (size_t)o0 * VOUT;
        float* p1 = out + outBase + (size_t)o1 * VOUT;
#pragma unroll
        for (int nt = 0; nt < 4; ++nt) {
            const int s = sBase + nt * 8 + 2 * lr;
            float2 v0, v1;
            v0.x = fmaf(rstd, acc[mt][nt][0], B0);
            v0.y = fmaf(rstd, acc[mt][nt][1], B0);
            v1.x = fmaf(rstd, acc[mt][nt][2], B1);
            v1.y = fmaf(rstd, acc[mt][nt][3], B1);
            stcs2(p0 + s, v0);
            stcs2(p1 + s, v1);
        }
    }
}

extern "C" void kernel_launch(void* const* d_in, const int* in_sizes, int n_in,
                              void* d_out, int out_size) {
    (void)in_sizes; (void)n_in; (void)out_size;
    const float* x     = (const float*)d_in[0];
    const float* w_ct  = (const float*)d_in[1];
    const float* b_ct  = (const float*)d_in[2];
    const float* gamma = (const float*)d_in[3];
    const float* beta  = (const float*)d_in[4];
    const float* w_pw  = (const float*)d_in[5];
    float* out = (float*)d_out;

    k_stats<<<128, 256>>>(x);
    k_prep<<<1, 256>>>(w_ct, b_ct, gamma, beta, w_pw);
    k_main<<<4096, 128>>>(x, w_ct, out);
}